// round 3
// baseline (speedup 1.0000x reference)
#include <cuda_runtime.h>

// LoTD dense multi-res grid trilinear interpolation.
// Levels: R = {16,32,64,128,256}, F = {4,4,4,2,2}.
// Offsets (floats): 0, 16384, 147456, 1196032, 5390336; total 38944768.
// input: [N,3] fp32 in [-1,1]; output: [N,16] fp32 (concat of per-level feats).

#define N_POINTS 1000000

__device__ __forceinline__ float4 lerp4(float4 a, float4 b, float w) {
    float4 r;
    r.x = a.x + (b.x - a.x) * w;  // matches a*(1-w)+b*w to fp32 rounding well enough (tol 1e-3)
    r.y = a.y + (b.y - a.y) * w;
    r.z = a.z + (b.z - a.z) * w;
    r.w = a.w + (b.w - a.w) * w;
    return r;
}

__device__ __forceinline__ float2 lerp2(float2 a, float2 b, float w) {
    float2 r;
    r.x = a.x + (b.x - a.x) * w;
    r.y = a.y + (b.y - a.y) * w;
    return r;
}

template <int R>
__device__ __forceinline__ void coords(float px, float py, float pz,
                                       int& x0, int& y0, int& z0,
                                       float& wx, float& wy, float& wz) {
    const float Rm1 = (float)(R - 1);
    float fx = fminf(fmaxf(px, 0.0f), 1.0f) * Rm1;
    float fy = fminf(fmaxf(py, 0.0f), 1.0f) * Rm1;
    float fz = fminf(fmaxf(pz, 0.0f), 1.0f) * Rm1;
    x0 = min((int)fx, R - 2);
    y0 = min((int)fy, R - 2);
    z0 = min((int)fz, R - 2);
    wx = fx - (float)x0;
    wy = fy - (float)y0;
    wz = fz - (float)z0;
}

// F = 4 level
template <int R>
__device__ __forceinline__ void interp_f4(const float* __restrict__ g,
                                          float px, float py, float pz,
                                          float* __restrict__ res) {
    int x0, y0, z0; float wx, wy, wz;
    coords<R>(px, py, pz, x0, y0, z0, wx, wy, wz);

    int i00 = ((x0 * R + y0) * R + z0) * 4;       // (x0,y0,z0)
    int i01 = ((x0 * R + (y0 + 1)) * R + z0) * 4; // (x0,y1,z0)
    int i10 = (((x0 + 1) * R + y0) * R + z0) * 4;
    int i11 = (((x0 + 1) * R + (y0 + 1)) * R + z0) * 4;

    const float4* g4 = (const float4*)g;
    // float index /4 -> float4 index
    float4 v000 = __ldg(g4 + (i00 >> 2));
    float4 v001 = __ldg(g4 + (i00 >> 2) + 1);
    float4 v010 = __ldg(g4 + (i01 >> 2));
    float4 v011 = __ldg(g4 + (i01 >> 2) + 1);
    float4 v100 = __ldg(g4 + (i10 >> 2));
    float4 v101 = __ldg(g4 + (i10 >> 2) + 1);
    float4 v110 = __ldg(g4 + (i11 >> 2));
    float4 v111 = __ldg(g4 + (i11 >> 2) + 1);

    float4 c00 = lerp4(v000, v001, wz);
    float4 c01 = lerp4(v010, v011, wz);
    float4 c10 = lerp4(v100, v101, wz);
    float4 c11 = lerp4(v110, v111, wz);
    float4 c0 = lerp4(c00, c01, wy);
    float4 c1 = lerp4(c10, c11, wy);
    float4 c = lerp4(c0, c1, wx);
    res[0] = c.x; res[1] = c.y; res[2] = c.z; res[3] = c.w;
}

// F = 2 level
template <int R>
__device__ __forceinline__ void interp_f2(const float* __restrict__ g,
                                          float px, float py, float pz,
                                          float* __restrict__ res) {
    int x0, y0, z0; float wx, wy, wz;
    coords<R>(px, py, pz, x0, y0, z0, wx, wy, wz);

    int i00 = ((x0 * R + y0) * R + z0) * 2;
    int i01 = ((x0 * R + (y0 + 1)) * R + z0) * 2;
    int i10 = (((x0 + 1) * R + y0) * R + z0) * 2;
    int i11 = (((x0 + 1) * R + (y0 + 1)) * R + z0) * 2;

    const float2* g2 = (const float2*)g;
    float2 v000 = __ldg(g2 + (i00 >> 1));
    float2 v001 = __ldg(g2 + (i00 >> 1) + 1);
    float2 v010 = __ldg(g2 + (i01 >> 1));
    float2 v011 = __ldg(g2 + (i01 >> 1) + 1);
    float2 v100 = __ldg(g2 + (i10 >> 1));
    float2 v101 = __ldg(g2 + (i10 >> 1) + 1);
    float2 v110 = __ldg(g2 + (i11 >> 1));
    float2 v111 = __ldg(g2 + (i11 >> 1) + 1);

    float2 c00 = lerp2(v000, v001, wz);
    float2 c01 = lerp2(v010, v011, wz);
    float2 c10 = lerp2(v100, v101, wz);
    float2 c11 = lerp2(v110, v111, wz);
    float2 c0 = lerp2(c00, c01, wy);
    float2 c1 = lerp2(c10, c11, wy);
    float2 c = lerp2(c0, c1, wx);
    res[0] = c.x; res[1] = c.y;
}

__global__ __launch_bounds__(256) void lotd_kernel(
    const float* __restrict__ inp,
    const float* __restrict__ params,
    float* __restrict__ out)
{
    int i = blockIdx.x * blockDim.x + threadIdx.x;
    if (i >= N_POINTS) return;

    float px = inp[3 * i + 0] * 0.5f + 0.5f;
    float py = inp[3 * i + 1] * 0.5f + 0.5f;
    float pz = inp[3 * i + 2] * 0.5f + 0.5f;

    float feats[16];
    interp_f4<16> (params + 0,        px, py, pz, feats + 0);
    interp_f4<32> (params + 16384,    px, py, pz, feats + 4);
    interp_f4<64> (params + 147456,   px, py, pz, feats + 8);
    interp_f2<128>(params + 1196032,  px, py, pz, feats + 12);
    interp_f2<256>(params + 5390336,  px, py, pz, feats + 14);

    float4* o4 = (float4*)(out + (size_t)i * 16);
    o4[0] = make_float4(feats[0],  feats[1],  feats[2],  feats[3]);
    o4[1] = make_float4(feats[4],  feats[5],  feats[6],  feats[7]);
    o4[2] = make_float4(feats[8],  feats[9],  feats[10], feats[11]);
    o4[3] = make_float4(feats[12], feats[13], feats[14], feats[15]);
}

extern "C" void kernel_launch(void* const* d_in, const int* in_sizes, int n_in,
                              void* d_out, int out_size) {
    const float* inp    = (const float*)d_in[0];
    const float* params = (const float*)d_in[1];
    float* out = (float*)d_out;
    int threads = 256;
    int blocks = (N_POINTS + threads - 1) / threads;
    lotd_kernel<<<blocks, threads>>>(inp, params, out);
}